// round 13
// baseline (speedup 1.0000x reference)
#include <cuda_runtime.h>
#include <cstdint>
#include <cmath>
#include <math.h>

// Problem constants (fixed by setup_inputs)
#define T_TOK    8192
#define D_MODEL  1024
#define F_FF     4096
#define N_EXP    8
#define CAPACITY 2560          // ceil(1.25 * 8192*2 / 8)
#define NASSIGN  (T_TOK * 2)

// ---------------- scratch (device globals: no allocation allowed) ----------------
__device__ int      g_expert[NASSIGN];
__device__ float    g_gate[NASSIGN];
__device__ int      g_pos[NASSIGN];
__device__ int      g_count[N_EXP];
__device__ int      g_rowtok[N_EXP * CAPACITY];
__device__ uint32_t g_h[(size_t)N_EXP * CAPACITY * F_FF];    // 335 MB (tf32 bits, K-major)
__device__ float    g_y[(size_t)N_EXP * CAPACITY * D_MODEL]; //  84 MB
// pre-converted tf32 operands
__device__ uint32_t g_xt [(size_t)T_TOK * D_MODEL];            // x, row-major [T][d]
__device__ uint32_t g_w1t[(size_t)N_EXP * F_FF * D_MODEL];     // W1^T: [e][f][d] (K-major, K=d)
__device__ uint32_t g_w2t[(size_t)N_EXP * D_MODEL * F_FF];     // W2^T: [e][d][f] (K-major, K=f)

// ---------------- helpers ----------------
__device__ __forceinline__ uint32_t su32(const void* p) {
    return (uint32_t)__cvta_generic_to_shared(p);
}
__device__ __forceinline__ uint32_t f2tf(float f) {
    uint32_t r; asm("cvt.rna.tf32.f32 %0, %1;" : "=r"(r) : "f"(f)); return r;
}
__device__ __forceinline__ void cpa16(uint32_t d, const void* s) {
    asm volatile("cp.async.cg.shared.global [%0], [%1], 16;" :: "r"(d), "l"(s));
}
__device__ __forceinline__ void cp_commit() { asm volatile("cp.async.commit_group;"); }
__device__ __forceinline__ void cp_wait0()  { asm volatile("cp.async.wait_group 0;" ::: "memory"); }

__device__ __forceinline__ void mma_tf32(float* c, const uint32_t* a, uint32_t b0, uint32_t b1) {
    asm volatile(
        "mma.sync.aligned.m16n8k8.row.col.f32.tf32.tf32.f32 "
        "{%0,%1,%2,%3}, {%4,%5,%6,%7}, {%8,%9}, {%0,%1,%2,%3};"
        : "+f"(c[0]), "+f"(c[1]), "+f"(c[2]), "+f"(c[3])
        : "r"(a[0]), "r"(a[1]), "r"(a[2]), "r"(a[3]), "r"(b0), "r"(b1));
}
// tf32-via-b16 ldmatrix: each 32-bit word = one tf32 element; x4 = 4 8x(4xtf32) tiles
__device__ __forceinline__ void ldsm4(uint32_t* r, uint32_t a) {
    asm volatile("ldmatrix.sync.aligned.m8n8.x4.shared.b16 {%0,%1,%2,%3}, [%4];"
        : "=r"(r[0]), "=r"(r[1]), "=r"(r[2]), "=r"(r[3]) : "r"(a));
}
__device__ __forceinline__ float gelu_exact(float v) {
    return 0.5f * v * (1.0f + erff(v * 0.70710678118654752440f));
}

// ---------------- 0a) tf32 convert (x: no transpose) ----------------
__global__ void tf32_conv_kernel(const float4* __restrict__ src, uint4* __restrict__ dst, int n4) {
    int i = blockIdx.x * blockDim.x + threadIdx.x;
    if (i < n4) {
        float4 v = src[i];
        uint4 o;
        o.x = f2tf(v.x); o.y = f2tf(v.y); o.z = f2tf(v.z); o.w = f2tf(v.w);
        dst[i] = o;
    }
}

// ---------------- 0b) tf32 convert + transpose: dst[e][c][r] = tf32(src[e][r][c]) ----
__global__ void conv_transpose_kernel(const float* __restrict__ src, uint32_t* __restrict__ dst,
                                      int R, int C) {
    __shared__ uint32_t tile[32][33];
    const int e  = blockIdx.z;
    const float* s = src + (size_t)e * R * C;
    uint32_t*    d = dst + (size_t)e * R * C;
    const int c0 = blockIdx.x * 32, r0 = blockIdx.y * 32;
    #pragma unroll
    for (int i = 0; i < 4; i++) {
        int r = r0 + threadIdx.y + i * 8;
        tile[threadIdx.y + i * 8][threadIdx.x] = f2tf(s[(size_t)r * C + c0 + threadIdx.x]);
    }
    __syncthreads();
    #pragma unroll
    for (int i = 0; i < 4; i++) {
        int rr = threadIdx.y + i * 8;
        d[(size_t)(c0 + rr) * R + r0 + threadIdx.x] = tile[threadIdx.x][rr];
    }
}

// ---------------- 1) router ----------------
__global__ void router_kernel(const float* __restrict__ x,
                              const float* __restrict__ Wr,
                              const float* __restrict__ br) {
    __shared__ float sW[D_MODEL * N_EXP];
    const int tid = threadIdx.x;
    for (int i = tid; i < D_MODEL * N_EXP / 4; i += blockDim.x)
        ((float4*)sW)[i] = ((const float4*)Wr)[i];
    __syncthreads();

    const int warp = tid >> 5, lane = tid & 31;
    const int tok = blockIdx.x * 8 + warp;
    const float* xr = x + (size_t)tok * D_MODEL;

    float a[8] = {0.f,0.f,0.f,0.f,0.f,0.f,0.f,0.f};
    for (int i = lane; i < D_MODEL; i += 32) {
        float xv = xr[i];
        const float* w = sW + i * N_EXP;
        #pragma unroll
        for (int e = 0; e < 8; e++) a[e] += xv * w[e];
    }
    #pragma unroll
    for (int e = 0; e < 8; e++) {
        #pragma unroll
        for (int off = 16; off; off >>= 1)
            a[e] += __shfl_xor_sync(0xffffffffu, a[e], off);
    }
    if (lane == 0) {
        #pragma unroll
        for (int e = 0; e < 8; e++) a[e] += br[e];
        int e0 = 0; float l0 = a[0];
        #pragma unroll
        for (int e = 1; e < 8; e++) if (a[e] > l0) { l0 = a[e]; e0 = e; }
        int e1 = -1; float l1 = -1e30f;
        #pragma unroll
        for (int e = 0; e < 8; e++) if (e != e0 && a[e] > l1) { l1 = a[e]; e1 = e; }
        float w0 = 1.f / (1.f + expf(l1 - l0));
        float w1 = 1.f / (1.f + expf(l0 - l1));
        g_expert[2*tok]   = e0;  g_expert[2*tok+1] = e1;
        g_gate[2*tok]     = w0;  g_gate[2*tok+1]   = w1;
    }
}

// ---------------- 2) FCFS positions + per-expert gather lists ----------------
__global__ void assign_kernel() {
    __shared__ int sc[1024][9];
    const int t = threadIdx.x;
    const int base = t * 16;

    #pragma unroll
    for (int e = 0; e < 8; e++) sc[t][e] = 0;
    for (int i = 0; i < 16; i++) sc[t][g_expert[base + i]]++;

    int loc[8], run[8];
    #pragma unroll
    for (int e = 0; e < 8; e++) { loc[e] = sc[t][e]; run[e] = loc[e]; }
    __syncthreads();

    for (int off = 1; off < 1024; off <<= 1) {
        int add[8];
        #pragma unroll
        for (int e = 0; e < 8; e++) add[e] = (t >= off) ? sc[t - off][e] : 0;
        __syncthreads();
        #pragma unroll
        for (int e = 0; e < 8; e++) { run[e] += add[e]; sc[t][e] = run[e]; }
        __syncthreads();
    }
    if (t == 1023) {
        #pragma unroll
        for (int e = 0; e < 8; e++)
            g_count[e] = run[e] < CAPACITY ? run[e] : CAPACITY;
    }
    #pragma unroll
    for (int e = 0; e < 8; e++) sc[t][e] = run[e] - loc[e];
    for (int i = 0; i < 16; i++) {
        int a = base + i;
        int e = g_expert[a];
        int p = sc[t][e]++;
        g_pos[a] = p;
        if (p < CAPACITY) g_rowtok[e * CAPACITY + p] = a >> 1;
    }
}

// ---------------- 3) grouped tf32 GEMM, 128x128 CTA tile, 64x64 warp tiles ----------
// 4 warps / 128 threads per CTA. A and B both staged row-major-in-K [128][20]
// (B pre-transposed to [N][K] in global). Fragments loaded via ldmatrix.x4
// (tf32-as-b16 trick): 8 LDSM + 32 HMMA per warp per k8 step.
template <bool FIRST>
__global__ __launch_bounds__(128, 2)
void moe_gemm(const uint32_t* __restrict__ X,
              const uint32_t* __restrict__ W,
              const float* __restrict__ bias) {
    constexpr int KTOT = FIRST ? D_MODEL : F_FF;
    constexpr int NTOT = FIRST ? F_FF : D_MODEL;
    constexpr int KIT  = KTOT / 16;

    __shared__ __align__(16) uint32_t As[2][128][20];  // 80B rows: 16B-aligned, LDSM-conflict-free
    __shared__ __align__(16) uint32_t Bs[2][128][20];

    const int e = blockIdx.z, mt = blockIdx.y, nt = blockIdx.x;
    const int cnt = g_count[e];
    if (mt * 128 >= cnt) return;

    const int tid = threadIdx.x, lane = tid & 31, warp = tid >> 5;
    const int wm = warp & 1, wn = warp >> 1;   // 2x2 warps -> 64x64 warp tiles

    const uint32_t* Ain = FIRST ? X : (const uint32_t*)g_h;

    // per-thread cp.async assignments: 4 A chunks + 4 B chunks of 16B per k16 stage
    const uint32_t* asrc[4]; uint32_t adst[4];
    const uint32_t* bsrc[4]; uint32_t bdst[4];
    #pragma unroll
    for (int j = 0; j < 4; j++) {
        int c = tid + j * 128;                // 0..511
        int row = c >> 2, seg = (c & 3) * 4;  // 4 x 16B per 16-float row
        if (FIRST) {
            int gr = mt * 128 + row;
            int tk = (gr < cnt) ? g_rowtok[e * CAPACITY + gr] : 0;  // safe garbage row
            asrc[j] = Ain + (size_t)tk * KTOT + seg;
        } else {
            asrc[j] = Ain + ((size_t)e * CAPACITY + mt * 128 + row) * (size_t)KTOT + seg;
        }
        adst[j] = su32(&As[0][row][seg]);
        bsrc[j] = W + ((size_t)e * NTOT + nt * 128 + row) * (size_t)KTOT + seg;
        bdst[j] = su32(&Bs[0][row][seg]);
    }
    constexpr uint32_t STAGE = 128 * 20 * 4;

    // per-lane ldmatrix row addresses (byte offsets within a stage)
    // A tile order: (m0-7,k0-3)(m8-15,k0-3)(m0-7,k4-7)(m8-15,k4-7)
    uint32_t aoff[4], boff[4];
    #pragma unroll
    for (int mf = 0; mf < 4; mf++) {
        int row = wm * 64 + mf * 16 + ((lane >> 3) & 1) * 8 + (lane & 7);
        aoff[mf] = su32(&As[0][0][0]) + (uint32_t)row * 80u + ((lane >> 4) & 1) * 16u;
    }
    // B tile order: (n0-7,k0-3)(n0-7,k4-7)(n8-15,k0-3)(n8-15,k4-7)
    #pragma unroll
    for (int np = 0; np < 4; np++) {
        int row = wn * 64 + np * 16 + ((lane >> 4) & 1) * 8 + (lane & 7);
        boff[np] = su32(&Bs[0][0][0]) + (uint32_t)row * 80u + ((lane >> 3) & 1) * 16u;
    }

    float acc[4][8][4];
    #pragma unroll
    for (int mf = 0; mf < 4; mf++)
        #pragma unroll
        for (int nf = 0; nf < 8; nf++)
            #pragma unroll
            for (int q = 0; q < 4; q++) acc[mf][nf][q] = 0.f;

    // prologue: stage 0
    #pragma unroll
    for (int j = 0; j < 4; j++) { cpa16(adst[j], asrc[j]); cpa16(bdst[j], bsrc[j]); }
    cp_commit();

    #pragma unroll 1
    for (int kt = 0; kt < KIT; kt++) {
        const int s = kt & 1;
        cp_wait0();
        __syncthreads();
        if (kt + 1 < KIT) {
            const uint32_t so = (uint32_t)(s ^ 1) * STAGE;
            #pragma unroll
            for (int j = 0; j < 4; j++) {
                cpa16(adst[j] + so, asrc[j] + (size_t)(kt + 1) * 16);
                cpa16(bdst[j] + so, bsrc[j] + (size_t)(kt + 1) * 16);
            }
            cp_commit();
        }
        const uint32_t sb = (uint32_t)s * STAGE;
        #pragma unroll
        for (int kk = 0; kk < 2; kk++) {         // two k8 steps (byte offset 0 / 32)
            const uint32_t ko = sb + kk * 32u;
            uint32_t a[4][4], b[4][4];
            #pragma unroll
            for (int mf = 0; mf < 4; mf++) ldsm4(a[mf], aoff[mf] + ko);
            #pragma unroll
            for (int np = 0; np < 4; np++) ldsm4(b[np], boff[np] + ko);
            #pragma unroll
            for (int mf = 0; mf < 4; mf++)
                #pragma unroll
                for (int nf = 0; nf < 8; nf++)
                    mma_tf32(acc[mf][nf], a[mf], b[nf >> 1][(nf & 1) * 2],
                             b[nf >> 1][(nf & 1) * 2 + 1]);
        }
    }

    // epilogue: bias (+gelu), write C
    const float* bp = bias + (size_t)e * NTOT + nt * 128 + wn * 64;
    const size_t cbase = ((size_t)e * CAPACITY + mt * 128 + wm * 64) * (size_t)NTOT
                       + (size_t)nt * 128 + wn * 64;
    #pragma unroll
    for (int mf = 0; mf < 4; mf++) {
        #pragma unroll
        for (int nf = 0; nf < 8; nf++) {
            int r  = mf * 16 + (lane >> 2);
            int cn = nf * 8 + 2 * (lane & 3);
            float bb0 = bp[cn], bb1 = bp[cn + 1];
            float v0 = acc[mf][nf][0] + bb0, v1 = acc[mf][nf][1] + bb1;
            float v2 = acc[mf][nf][2] + bb0, v3 = acc[mf][nf][3] + bb1;
            if (FIRST) {
                uint32_t u0 = f2tf(gelu_exact(v0)), u1 = f2tf(gelu_exact(v1));
                uint32_t u2 = f2tf(gelu_exact(v2)), u3 = f2tf(gelu_exact(v3));
                *(uint2*)(g_h + cbase + (size_t)r * NTOT + cn)       = make_uint2(u0, u1);
                *(uint2*)(g_h + cbase + (size_t)(r + 8) * NTOT + cn) = make_uint2(u2, u3);
            } else {
                *(float2*)(g_y + cbase + (size_t)r * NTOT + cn)       = make_float2(v0, v1);
                *(float2*)(g_y + cbase + (size_t)(r + 8) * NTOT + cn) = make_float2(v2, v3);
            }
        }
    }
}

// ---------------- 4) combine ----------------
__global__ void combine_kernel(float* __restrict__ out) {
    const int idx = blockIdx.x * blockDim.x + threadIdx.x;
    const int tok = idx >> 10;
    const int col = idx & (D_MODEL - 1);
    float acc = 0.f;
    #pragma unroll
    for (int kk = 0; kk < 2; kk++) {
        int a = 2 * tok + kk;
        int p = g_pos[a];
        if (p < CAPACITY) {
            int ee = g_expert[a];
            acc += g_gate[a] * g_y[((size_t)ee * CAPACITY + p) * D_MODEL + col];
        }
    }
    out[idx] = acc;
}

// ---------------- launch ----------------
extern "C" void kernel_launch(void* const* d_in, const int* in_sizes, int n_in,
                              void* d_out, int out_size) {
    (void)in_sizes; (void)n_in; (void)out_size;
    const float* x  = (const float*)d_in[0];
    const float* Wr = (const float*)d_in[1];
    const float* br = (const float*)d_in[2];
    const float* W1 = (const float*)d_in[3];
    const float* b1 = (const float*)d_in[4];
    const float* W2 = (const float*)d_in[5];
    const float* b2 = (const float*)d_in[6];
    float* out = (float*)d_out;

    uint32_t *xt_p, *w1t_p, *w2t_p;
    cudaGetSymbolAddress((void**)&xt_p,  g_xt);
    cudaGetSymbolAddress((void**)&w1t_p, g_w1t);
    cudaGetSymbolAddress((void**)&w2t_p, g_w2t);

    // x: tf32 convert; W1/W2: tf32 convert + transpose to [N][K]
    {
        const int nx = T_TOK * D_MODEL / 4;
        tf32_conv_kernel<<<(nx + 255) / 256, 256>>>((const float4*)x, (uint4*)xt_p, nx);
        dim3 blk(32, 8);
        conv_transpose_kernel<<<dim3(F_FF / 32,    D_MODEL / 32, N_EXP), blk>>>(W1, w1t_p, D_MODEL, F_FF);
        conv_transpose_kernel<<<dim3(D_MODEL / 32, F_FF / 32,    N_EXP), blk>>>(W2, w2t_p, F_FF, D_MODEL);
    }

    router_kernel<<<T_TOK / 8, 256>>>(x, Wr, br);
    assign_kernel<<<1, 1024>>>();
    moe_gemm<true ><<<dim3(F_FF / 128,    CAPACITY / 128, N_EXP), 128>>>(xt_p,    w1t_p, b1);
    moe_gemm<false><<<dim3(D_MODEL / 128, CAPACITY / 128, N_EXP), 128>>>(nullptr, w2t_p, b2);
    combine_kernel<<<(T_TOK * D_MODEL) / 256, 256>>>(out);
}

// round 14
// speedup vs baseline: 1.3270x; 1.3270x over previous
#include <cuda_runtime.h>
#include <cstdint>
#include <cmath>
#include <math.h>

// Problem constants (fixed by setup_inputs)
#define T_TOK    8192
#define D_MODEL  1024
#define F_FF     4096
#define N_EXP    8
#define CAPACITY 2560          // ceil(1.25 * 8192*2 / 8)
#define NASSIGN  (T_TOK * 2)

// ---------------- scratch (device globals: no allocation allowed) ----------------
__device__ int      g_expert[NASSIGN];
__device__ float    g_gate[NASSIGN];
__device__ int      g_pos[NASSIGN];
__device__ int      g_count[N_EXP];
__device__ int      g_rowtok[N_EXP * CAPACITY];
__device__ uint32_t g_h[(size_t)N_EXP * CAPACITY * F_FF];    // 335 MB (tf32 bits, K-major)
__device__ float    g_y[(size_t)N_EXP * CAPACITY * D_MODEL]; //  84 MB
// pre-converted tf32 operands
__device__ uint32_t g_xt [(size_t)T_TOK * D_MODEL];            // x, row-major [T][d]
__device__ uint32_t g_w1t[(size_t)N_EXP * F_FF * D_MODEL];     // W1^T: [e][f][d] (K-major, K=d)
__device__ uint32_t g_w2t[(size_t)N_EXP * D_MODEL * F_FF];     // W2^T: [e][d][f] (K-major, K=f)

// ---------------- helpers ----------------
__device__ __forceinline__ uint32_t su32(const void* p) {
    return (uint32_t)__cvta_generic_to_shared(p);
}
__device__ __forceinline__ uint32_t f2tf(float f) {
    uint32_t r; asm("cvt.rna.tf32.f32 %0, %1;" : "=r"(r) : "f"(f)); return r;
}
__device__ __forceinline__ void cpa16(uint32_t d, const void* s) {
    asm volatile("cp.async.cg.shared.global [%0], [%1], 16;" :: "r"(d), "l"(s));
}
__device__ __forceinline__ void cp_commit() { asm volatile("cp.async.commit_group;"); }
__device__ __forceinline__ void cp_wait0()  { asm volatile("cp.async.wait_group 0;" ::: "memory"); }

__device__ __forceinline__ void mma_tf32(float* c, const uint32_t* a, uint32_t b0, uint32_t b1) {
    asm volatile(
        "mma.sync.aligned.m16n8k8.row.col.f32.tf32.tf32.f32 "
        "{%0,%1,%2,%3}, {%4,%5,%6,%7}, {%8,%9}, {%0,%1,%2,%3};"
        : "+f"(c[0]), "+f"(c[1]), "+f"(c[2]), "+f"(c[3])
        : "r"(a[0]), "r"(a[1]), "r"(a[2]), "r"(a[3]), "r"(b0), "r"(b1));
}
// tf32-via-b16 ldmatrix: each 32-bit word = one tf32 element; x4 = 4 tiles of 8x4 tf32
__device__ __forceinline__ void ldsm4(uint32_t* r, uint32_t a) {
    asm volatile("ldmatrix.sync.aligned.m8n8.x4.shared.b16 {%0,%1,%2,%3}, [%4];"
        : "=r"(r[0]), "=r"(r[1]), "=r"(r[2]), "=r"(r[3]) : "r"(a));
}
__device__ __forceinline__ float gelu_exact(float v) {
    return 0.5f * v * (1.0f + erff(v * 0.70710678118654752440f));
}

// ---------------- 0a) tf32 convert (x: no transpose) ----------------
__global__ void tf32_conv_kernel(const float4* __restrict__ src, uint4* __restrict__ dst, int n4) {
    int i = blockIdx.x * blockDim.x + threadIdx.x;
    if (i < n4) {
        float4 v = src[i];
        uint4 o;
        o.x = f2tf(v.x); o.y = f2tf(v.y); o.z = f2tf(v.z); o.w = f2tf(v.w);
        dst[i] = o;
    }
}

// ---------------- 0b) tf32 convert + transpose: dst[e][c][r] = tf32(src[e][r][c]) ----
__global__ void conv_transpose_kernel(const float* __restrict__ src, uint32_t* __restrict__ dst,
                                      int R, int C) {
    __shared__ uint32_t tile[32][33];
    const int e  = blockIdx.z;
    const float* s = src + (size_t)e * R * C;
    uint32_t*    d = dst + (size_t)e * R * C;
    const int c0 = blockIdx.x * 32, r0 = blockIdx.y * 32;
    #pragma unroll
    for (int i = 0; i < 4; i++) {
        int r = r0 + threadIdx.y + i * 8;
        tile[threadIdx.y + i * 8][threadIdx.x] = f2tf(s[(size_t)r * C + c0 + threadIdx.x]);
    }
    __syncthreads();
    #pragma unroll
    for (int i = 0; i < 4; i++) {
        int rr = threadIdx.y + i * 8;
        d[(size_t)(c0 + rr) * R + r0 + threadIdx.x] = tile[threadIdx.x][rr];
    }
}

// ---------------- 1) router ----------------
__global__ void router_kernel(const float* __restrict__ x,
                              const float* __restrict__ Wr,
                              const float* __restrict__ br) {
    __shared__ float sW[D_MODEL * N_EXP];
    const int tid = threadIdx.x;
    for (int i = tid; i < D_MODEL * N_EXP / 4; i += blockDim.x)
        ((float4*)sW)[i] = ((const float4*)Wr)[i];
    __syncthreads();

    const int warp = tid >> 5, lane = tid & 31;
    const int tok = blockIdx.x * 8 + warp;
    const float* xr = x + (size_t)tok * D_MODEL;

    float a[8] = {0.f,0.f,0.f,0.f,0.f,0.f,0.f,0.f};
    for (int i = lane; i < D_MODEL; i += 32) {
        float xv = xr[i];
        const float* w = sW + i * N_EXP;
        #pragma unroll
        for (int e = 0; e < 8; e++) a[e] += xv * w[e];
    }
    #pragma unroll
    for (int e = 0; e < 8; e++) {
        #pragma unroll
        for (int off = 16; off; off >>= 1)
            a[e] += __shfl_xor_sync(0xffffffffu, a[e], off);
    }
    if (lane == 0) {
        #pragma unroll
        for (int e = 0; e < 8; e++) a[e] += br[e];
        int e0 = 0; float l0 = a[0];
        #pragma unroll
        for (int e = 1; e < 8; e++) if (a[e] > l0) { l0 = a[e]; e0 = e; }
        int e1 = -1; float l1 = -1e30f;
        #pragma unroll
        for (int e = 0; e < 8; e++) if (e != e0 && a[e] > l1) { l1 = a[e]; e1 = e; }
        float w0 = 1.f / (1.f + expf(l1 - l0));
        float w1 = 1.f / (1.f + expf(l0 - l1));
        g_expert[2*tok]   = e0;  g_expert[2*tok+1] = e1;
        g_gate[2*tok]     = w0;  g_gate[2*tok+1]   = w1;
    }
}

// ---------------- 2) FCFS positions + per-expert gather lists ----------------
__global__ void assign_kernel() {
    __shared__ int sc[1024][9];
    const int t = threadIdx.x;
    const int base = t * 16;

    #pragma unroll
    for (int e = 0; e < 8; e++) sc[t][e] = 0;
    for (int i = 0; i < 16; i++) sc[t][g_expert[base + i]]++;

    int loc[8], run[8];
    #pragma unroll
    for (int e = 0; e < 8; e++) { loc[e] = sc[t][e]; run[e] = loc[e]; }
    __syncthreads();

    for (int off = 1; off < 1024; off <<= 1) {
        int add[8];
        #pragma unroll
        for (int e = 0; e < 8; e++) add[e] = (t >= off) ? sc[t - off][e] : 0;
        __syncthreads();
        #pragma unroll
        for (int e = 0; e < 8; e++) { run[e] += add[e]; sc[t][e] = run[e]; }
        __syncthreads();
    }
    if (t == 1023) {
        #pragma unroll
        for (int e = 0; e < 8; e++)
            g_count[e] = run[e] < CAPACITY ? run[e] : CAPACITY;
    }
    #pragma unroll
    for (int e = 0; e < 8; e++) sc[t][e] = run[e] - loc[e];
    for (int i = 0; i < 16; i++) {
        int a = base + i;
        int e = g_expert[a];
        int p = sc[t][e]++;
        g_pos[a] = p;
        if (p < CAPACITY) g_rowtok[e * CAPACITY + p] = a >> 1;
    }
}

// ---------------- 3) grouped tf32 GEMM, 128x128 CTA tile, 32x64 warp tiles ----------
// 8 warps / 256 threads (R9 occupancy shape: 2 CTAs/SM = 16 warps/SM).
// A and B both staged K-major [128][20]; fragments via ldmatrix.x4 (tf32-as-b16):
// 6 LDSM + 16 HMMA per warp per k8 step (was 24 scalar LDS + 16 HMMA).
template <bool FIRST>
__global__ __launch_bounds__(256, 2)
void moe_gemm(const uint32_t* __restrict__ X,
              const uint32_t* __restrict__ W,
              const float* __restrict__ bias) {
    constexpr int KTOT = FIRST ? D_MODEL : F_FF;
    constexpr int NTOT = FIRST ? F_FF : D_MODEL;
    constexpr int KIT  = KTOT / 16;

    __shared__ __align__(16) uint32_t As[2][128][20];  // 80B rows: LDSM conflict-free
    __shared__ __align__(16) uint32_t Bs[2][128][20];

    const int e = blockIdx.z, mt = blockIdx.y, nt = blockIdx.x;
    const int cnt = g_count[e];
    if (mt * 128 >= cnt) return;

    const int tid = threadIdx.x, lane = tid & 31, warp = tid >> 5;
    const int wm = warp & 3, wn = warp >> 2;   // 4 (M) x 2 (N) warps -> 32x64 warp tiles

    const uint32_t* Ain = FIRST ? X : (const uint32_t*)g_h;

    // per-thread cp.async assignments: 2 A chunks + 2 B chunks of 16B per k16 stage
    const uint32_t* asrc[2]; uint32_t adst[2];
    const uint32_t* bsrc[2]; uint32_t bdst[2];
    #pragma unroll
    for (int j = 0; j < 2; j++) {
        int c = tid + j * 256;                // 0..511
        int row = c >> 2, seg = (c & 3) * 4;  // 4 x 16B per 16-float row
        if (FIRST) {
            int gr = mt * 128 + row;
            int tk = (gr < cnt) ? g_rowtok[e * CAPACITY + gr] : 0;  // safe garbage row
            asrc[j] = Ain + (size_t)tk * KTOT + seg;
        } else {
            asrc[j] = Ain + ((size_t)e * CAPACITY + mt * 128 + row) * (size_t)KTOT + seg;
        }
        adst[j] = su32(&As[0][row][seg]);
        bsrc[j] = W + ((size_t)e * NTOT + nt * 128 + row) * (size_t)KTOT + seg;
        bdst[j] = su32(&Bs[0][row][seg]);
    }
    constexpr uint32_t STAGE = 128 * 20 * 4;

    // ldmatrix lane addresses (verified mapping from R13):
    // A (m16xk8 frag per mf): mats = (m0-7,k0-3)(m8-15,k0-3)(m0-7,k4-7)(m8-15,k4-7)
    uint32_t aoff[2], boff[4];
    #pragma unroll
    for (int mf = 0; mf < 2; mf++) {
        int row = wm * 32 + mf * 16 + ((lane >> 3) & 1) * 8 + (lane & 7);
        aoff[mf] = su32(&As[0][0][0]) + (uint32_t)row * 80u + ((lane >> 4) & 1) * 16u;
    }
    // B (n16xk8 per np): mats = (n0-7,k0-3)(n0-7,k4-7)(n8-15,k0-3)(n8-15,k4-7)
    #pragma unroll
    for (int np = 0; np < 4; np++) {
        int row = wn * 64 + np * 16 + ((lane >> 4) & 1) * 8 + (lane & 7);
        boff[np] = su32(&Bs[0][0][0]) + (uint32_t)row * 80u + ((lane >> 3) & 1) * 16u;
    }

    float acc[2][8][4];
    #pragma unroll
    for (int mf = 0; mf < 2; mf++)
        #pragma unroll
        for (int nf = 0; nf < 8; nf++)
            #pragma unroll
            for (int q = 0; q < 4; q++) acc[mf][nf][q] = 0.f;

    // prologue: stage 0
    #pragma unroll
    for (int j = 0; j < 2; j++) { cpa16(adst[j], asrc[j]); cpa16(bdst[j], bsrc[j]); }
    cp_commit();

    #pragma unroll 1
    for (int kt = 0; kt < KIT; kt++) {
        const int s = kt & 1;
        cp_wait0();
        __syncthreads();
        if (kt + 1 < KIT) {
            const uint32_t so = (uint32_t)(s ^ 1) * STAGE;
            #pragma unroll
            for (int j = 0; j < 2; j++) {
                cpa16(adst[j] + so, asrc[j] + (size_t)(kt + 1) * 16);
                cpa16(bdst[j] + so, bsrc[j] + (size_t)(kt + 1) * 16);
            }
            cp_commit();
        }
        const uint32_t sb = (uint32_t)s * STAGE;
        #pragma unroll
        for (int kk = 0; kk < 2; kk++) {       // two k8 steps (byte offset 0 / 32)
            const uint32_t ko = sb + kk * 32u;
            uint32_t a[2][4];
            ldsm4(a[0], aoff[0] + ko);
            ldsm4(a[1], aoff[1] + ko);
            #pragma unroll
            for (int np = 0; np < 4; np++) {   // B LDSM interleaved with its 4 MMAs
                uint32_t b[4];
                ldsm4(b, boff[np] + ko);
                mma_tf32(acc[0][2*np    ], a[0], b[0], b[1]);
                mma_tf32(acc[1][2*np    ], a[1], b[0], b[1]);
                mma_tf32(acc[0][2*np + 1], a[0], b[2], b[3]);
                mma_tf32(acc[1][2*np + 1], a[1], b[2], b[3]);
            }
        }
    }

    // epilogue: bias (+gelu), write C
    const float* bp = bias + (size_t)e * NTOT + nt * 128 + wn * 64;
    const size_t cbase = ((size_t)e * CAPACITY + mt * 128 + wm * 32) * (size_t)NTOT
                       + (size_t)nt * 128 + wn * 64;
    #pragma unroll
    for (int mf = 0; mf < 2; mf++) {
        #pragma unroll
        for (int nf = 0; nf < 8; nf++) {
            int r  = mf * 16 + (lane >> 2);
            int cn = nf * 8 + 2 * (lane & 3);
            float bb0 = bp[cn], bb1 = bp[cn + 1];
            float v0 = acc[mf][nf][0] + bb0, v1 = acc[mf][nf][1] + bb1;
            float v2 = acc[mf][nf][2] + bb0, v3 = acc[mf][nf][3] + bb1;
            if (FIRST) {
                uint32_t u0 = f2tf(gelu_exact(v0)), u1 = f2tf(gelu_exact(v1));
                uint32_t u2 = f2tf(gelu_exact(v2)), u3 = f2tf(gelu_exact(v3));
                *(uint2*)(g_h + cbase + (size_t)r * NTOT + cn)       = make_uint2(u0, u1);
                *(uint2*)(g_h + cbase + (size_t)(r + 8) * NTOT + cn) = make_uint2(u2, u3);
            } else {
                *(float2*)(g_y + cbase + (size_t)r * NTOT + cn)       = make_float2(v0, v1);
                *(float2*)(g_y + cbase + (size_t)(r + 8) * NTOT + cn) = make_float2(v2, v3);
            }
        }
    }
}

// ---------------- 4) combine ----------------
__global__ void combine_kernel(float* __restrict__ out) {
    const int idx = blockIdx.x * blockDim.x + threadIdx.x;
    const int tok = idx >> 10;
    const int col = idx & (D_MODEL - 1);
    float acc = 0.f;
    #pragma unroll
    for (int kk = 0; kk < 2; kk++) {
        int a = 2 * tok + kk;
        int p = g_pos[a];
        if (p < CAPACITY) {
            int ee = g_expert[a];
            acc += g_gate[a] * g_y[((size_t)ee * CAPACITY + p) * D_MODEL + col];
        }
    }
    out[idx] = acc;
}

// ---------------- launch ----------------
extern "C" void kernel_launch(void* const* d_in, const int* in_sizes, int n_in,
                              void* d_out, int out_size) {
    (void)in_sizes; (void)n_in; (void)out_size;
    const float* x  = (const float*)d_in[0];
    const float* Wr = (const float*)d_in[1];
    const float* br = (const float*)d_in[2];
    const float* W1 = (const float*)d_in[3];
    const float* b1 = (const float*)d_in[4];
    const float* W2 = (const float*)d_in[5];
    const float* b2 = (const float*)d_in[6];
    float* out = (float*)d_out;

    uint32_t *xt_p, *w1t_p, *w2t_p;
    cudaGetSymbolAddress((void**)&xt_p,  g_xt);
    cudaGetSymbolAddress((void**)&w1t_p, g_w1t);
    cudaGetSymbolAddress((void**)&w2t_p, g_w2t);

    // x: tf32 convert; W1/W2: tf32 convert + transpose to [N][K]
    {
        const int nx = T_TOK * D_MODEL / 4;
        tf32_conv_kernel<<<(nx + 255) / 256, 256>>>((const float4*)x, (uint4*)xt_p, nx);
        dim3 blk(32, 8);
        conv_transpose_kernel<<<dim3(F_FF / 32,    D_MODEL / 32, N_EXP), blk>>>(W1, w1t_p, D_MODEL, F_FF);
        conv_transpose_kernel<<<dim3(D_MODEL / 32, F_FF / 32,    N_EXP), blk>>>(W2, w2t_p, F_FF, D_MODEL);
    }

    router_kernel<<<T_TOK / 8, 256>>>(x, Wr, br);
    assign_kernel<<<1, 1024>>>();
    moe_gemm<true ><<<dim3(F_FF / 128,    CAPACITY / 128, N_EXP), 256>>>(xt_p,    w1t_p, b1);
    moe_gemm<false><<<dim3(D_MODEL / 128, CAPACITY / 128, N_EXP), 256>>>(nullptr, w2t_p, b2);
    combine_kernel<<<(T_TOK * D_MODEL) / 256, 256>>>(out);
}

// round 15
// speedup vs baseline: 2.3146x; 1.7443x over previous
#include <cuda_runtime.h>
#include <cuda_fp16.h>
#include <cstdint>
#include <cmath>
#include <math.h>

// Problem constants (fixed by setup_inputs)
#define T_TOK    8192
#define D_MODEL  1024
#define F_FF     4096
#define N_EXP    8
#define CAPACITY 2560          // ceil(1.25 * 8192*2 / 8)
#define NASSIGN  (T_TOK * 2)

// ---------------- scratch (device globals: no allocation allowed) ----------------
__device__ int    g_expert[NASSIGN];
__device__ float  g_gate[NASSIGN];
__device__ int    g_pos[NASSIGN];
__device__ int    g_count[N_EXP];
__device__ int    g_rowtok[N_EXP * CAPACITY];
__device__ __half g_h[(size_t)N_EXP * CAPACITY * F_FF];     // 168 MB (fp16, K-major)
__device__ float  g_y[(size_t)N_EXP * CAPACITY * D_MODEL];  //  84 MB
// pre-converted fp16 operands
__device__ __half g_xh [(size_t)T_TOK * D_MODEL];             // x, row-major [T][d]
__device__ __half g_w1h[(size_t)N_EXP * F_FF * D_MODEL];      // W1^T: [e][f][d] (K-major, K=d)
__device__ __half g_w2h[(size_t)N_EXP * D_MODEL * F_FF];      // W2^T: [e][d][f] (K-major, K=f)

// ---------------- helpers ----------------
__device__ __forceinline__ uint32_t su32(const void* p) {
    return (uint32_t)__cvta_generic_to_shared(p);
}
__device__ __forceinline__ void cpa16(uint32_t d, const void* s) {
    asm volatile("cp.async.cg.shared.global [%0], [%1], 16;" :: "r"(d), "l"(s));
}
__device__ __forceinline__ void cp_commit() { asm volatile("cp.async.commit_group;"); }
__device__ __forceinline__ void cp_wait0()  { asm volatile("cp.async.wait_group 0;" ::: "memory"); }

// m16n8k16 fp16 MMA, fp32 accumulate
__device__ __forceinline__ void mma_f16(float* c, const uint32_t* a, uint32_t b0, uint32_t b1) {
    asm volatile(
        "mma.sync.aligned.m16n8k16.row.col.f32.f16.f16.f32 "
        "{%0,%1,%2,%3}, {%4,%5,%6,%7}, {%8,%9}, {%0,%1,%2,%3};"
        : "+f"(c[0]), "+f"(c[1]), "+f"(c[2]), "+f"(c[3])
        : "r"(a[0]), "r"(a[1]), "r"(a[2]), "r"(a[3]), "r"(b0), "r"(b1));
}
__device__ __forceinline__ void ldsm4(uint32_t* r, uint32_t a) {
    asm volatile("ldmatrix.sync.aligned.m8n8.x4.shared.b16 {%0,%1,%2,%3}, [%4];"
        : "=r"(r[0]), "=r"(r[1]), "=r"(r[2]), "=r"(r[3]) : "r"(a));
}
__device__ __forceinline__ float gelu_exact(float v) {
    return 0.5f * v * (1.0f + erff(v * 0.70710678118654752440f));
}

// ---------------- 0a) fp16 convert (x: no transpose), 8 elems/thread ----------------
__global__ void f2h_kernel(const float4* __restrict__ src, uint4* __restrict__ dst, int n8) {
    int i = blockIdx.x * blockDim.x + threadIdx.x;
    if (i < n8) {
        float4 v0 = src[2 * i], v1 = src[2 * i + 1];
        __half2 h0 = __floats2half2_rn(v0.x, v0.y);
        __half2 h1 = __floats2half2_rn(v0.z, v0.w);
        __half2 h2 = __floats2half2_rn(v1.x, v1.y);
        __half2 h3 = __floats2half2_rn(v1.z, v1.w);
        uint4 o;
        o.x = *(uint32_t*)&h0; o.y = *(uint32_t*)&h1;
        o.z = *(uint32_t*)&h2; o.w = *(uint32_t*)&h3;
        dst[i] = o;
    }
}

// ---------------- 0b) fp16 convert + transpose: dst[e][c][r] = h(src[e][r][c]) -------
__global__ void conv_transpose_kernel(const float* __restrict__ src, __half* __restrict__ dst,
                                      int R, int C) {
    __shared__ unsigned short tile[32][33];
    const int e  = blockIdx.z;
    const float* s = src + (size_t)e * R * C;
    __half*      d = dst + (size_t)e * R * C;
    const int c0 = blockIdx.x * 32, r0 = blockIdx.y * 32;
    #pragma unroll
    for (int i = 0; i < 4; i++) {
        int r = r0 + threadIdx.y + i * 8;
        __half h = __float2half_rn(s[(size_t)r * C + c0 + threadIdx.x]);
        tile[threadIdx.y + i * 8][threadIdx.x] = *(unsigned short*)&h;
    }
    __syncthreads();
    #pragma unroll
    for (int i = 0; i < 4; i++) {
        int rr = threadIdx.y + i * 8;
        unsigned short u = tile[threadIdx.x][rr];
        d[(size_t)(c0 + rr) * R + r0 + threadIdx.x] = *(__half*)&u;
    }
}

// ---------------- 1) router ----------------
__global__ void router_kernel(const float* __restrict__ x,
                              const float* __restrict__ Wr,
                              const float* __restrict__ br) {
    __shared__ float sW[D_MODEL * N_EXP];
    const int tid = threadIdx.x;
    for (int i = tid; i < D_MODEL * N_EXP / 4; i += blockDim.x)
        ((float4*)sW)[i] = ((const float4*)Wr)[i];
    __syncthreads();

    const int warp = tid >> 5, lane = tid & 31;
    const int tok = blockIdx.x * 8 + warp;
    const float* xr = x + (size_t)tok * D_MODEL;

    float a[8] = {0.f,0.f,0.f,0.f,0.f,0.f,0.f,0.f};
    for (int i = lane; i < D_MODEL; i += 32) {
        float xv = xr[i];
        const float* w = sW + i * N_EXP;
        #pragma unroll
        for (int e = 0; e < 8; e++) a[e] += xv * w[e];
    }
    #pragma unroll
    for (int e = 0; e < 8; e++) {
        #pragma unroll
        for (int off = 16; off; off >>= 1)
            a[e] += __shfl_xor_sync(0xffffffffu, a[e], off);
    }
    if (lane == 0) {
        #pragma unroll
        for (int e = 0; e < 8; e++) a[e] += br[e];
        int e0 = 0; float l0 = a[0];
        #pragma unroll
        for (int e = 1; e < 8; e++) if (a[e] > l0) { l0 = a[e]; e0 = e; }
        int e1 = -1; float l1 = -1e30f;
        #pragma unroll
        for (int e = 0; e < 8; e++) if (e != e0 && a[e] > l1) { l1 = a[e]; e1 = e; }
        float w0 = 1.f / (1.f + expf(l1 - l0));
        float w1 = 1.f / (1.f + expf(l0 - l1));
        g_expert[2*tok]   = e0;  g_expert[2*tok+1] = e1;
        g_gate[2*tok]     = w0;  g_gate[2*tok+1]   = w1;
    }
}

// ---------------- 2) FCFS positions + per-expert gather lists ----------------
__global__ void assign_kernel() {
    __shared__ int sc[1024][9];
    const int t = threadIdx.x;
    const int base = t * 16;

    #pragma unroll
    for (int e = 0; e < 8; e++) sc[t][e] = 0;
    for (int i = 0; i < 16; i++) sc[t][g_expert[base + i]]++;

    int loc[8], run[8];
    #pragma unroll
    for (int e = 0; e < 8; e++) { loc[e] = sc[t][e]; run[e] = loc[e]; }
    __syncthreads();

    for (int off = 1; off < 1024; off <<= 1) {
        int add[8];
        #pragma unroll
        for (int e = 0; e < 8; e++) add[e] = (t >= off) ? sc[t - off][e] : 0;
        __syncthreads();
        #pragma unroll
        for (int e = 0; e < 8; e++) { run[e] += add[e]; sc[t][e] = run[e]; }
        __syncthreads();
    }
    if (t == 1023) {
        #pragma unroll
        for (int e = 0; e < 8; e++)
            g_count[e] = run[e] < CAPACITY ? run[e] : CAPACITY;
    }
    #pragma unroll
    for (int e = 0; e < 8; e++) sc[t][e] = run[e] - loc[e];
    for (int i = 0; i < 16; i++) {
        int a = base + i;
        int e = g_expert[a];
        int p = sc[t][e]++;
        g_pos[a] = p;
        if (p < CAPACITY) g_rowtok[e * CAPACITY + p] = a >> 1;
    }
}

// ---------------- 3) grouped fp16 GEMM, 128x128 CTA tile, 32x64 warp tiles ----------
// 8 warps / 256 threads, 2 CTAs/SM. Stage = k32 fp16 (rows 64B data + 16B pad = 80B
// stride, conflict-free ldmatrix). Per warp per k16 step: 6 LDSM + 16 HMMA(m16n8k16).
template <bool FIRST>
__global__ __launch_bounds__(256, 2)
void moe_gemm(const __half* __restrict__ X,
              const __half* __restrict__ W,
              const float* __restrict__ bias) {
    constexpr int KTOT = FIRST ? D_MODEL : F_FF;
    constexpr int NTOT = FIRST ? F_FF : D_MODEL;
    constexpr int KIT  = KTOT / 32;

    __shared__ __align__(16) __half As[2][128][40];  // 80B rows
    __shared__ __align__(16) __half Bs[2][128][40];

    const int e = blockIdx.z, mt = blockIdx.y, nt = blockIdx.x;
    const int cnt = g_count[e];
    if (mt * 128 >= cnt) return;

    const int tid = threadIdx.x, lane = tid & 31, warp = tid >> 5;
    const int wm = warp & 3, wn = warp >> 2;   // 4 (M) x 2 (N) warps -> 32x64 warp tiles

    const __half* Ain = FIRST ? X : (const __half*)g_h;

    // per-thread cp.async assignments: 2 A chunks + 2 B chunks of 16B per k32 stage
    const __half* asrc[2]; uint32_t adst[2];
    const __half* bsrc[2]; uint32_t bdst[2];
    #pragma unroll
    for (int j = 0; j < 2; j++) {
        int c = tid + j * 256;                // 0..511
        int row = c >> 2, seg = (c & 3) * 8;  // 4 x 16B (8 halves) per 32-half row
        if (FIRST) {
            int gr = mt * 128 + row;
            int tk = (gr < cnt) ? g_rowtok[e * CAPACITY + gr] : 0;  // safe garbage row
            asrc[j] = Ain + (size_t)tk * KTOT + seg;
        } else {
            asrc[j] = Ain + ((size_t)e * CAPACITY + mt * 128 + row) * (size_t)KTOT + seg;
        }
        adst[j] = su32(&As[0][row][seg]);
        bsrc[j] = W + ((size_t)e * NTOT + nt * 128 + row) * (size_t)KTOT + seg;
        bdst[j] = su32(&Bs[0][row][seg]);
    }
    constexpr uint32_t STAGE = 128 * 40 * 2;  // bytes per operand stage

    // ldmatrix lane addresses (canonical fp16 m16n8k16 fragment mapping)
    uint32_t aoff[2], boff[4];
    #pragma unroll
    for (int mf = 0; mf < 2; mf++) {
        int row = wm * 32 + mf * 16 + ((lane >> 3) & 1) * 8 + (lane & 7);
        aoff[mf] = su32(&As[0][0][0]) + (uint32_t)row * 80u + ((lane >> 4) & 1) * 16u;
    }
    #pragma unroll
    for (int np = 0; np < 4; np++) {
        int row = wn * 64 + np * 16 + ((lane >> 4) & 1) * 8 + (lane & 7);
        boff[np] = su32(&Bs[0][0][0]) + (uint32_t)row * 80u + ((lane >> 3) & 1) * 16u;
    }

    float acc[2][8][4];
    #pragma unroll
    for (int mf = 0; mf < 2; mf++)
        #pragma unroll
        for (int nf = 0; nf < 8; nf++)
            #pragma unroll
            for (int q = 0; q < 4; q++) acc[mf][nf][q] = 0.f;

    // prologue: stage 0
    #pragma unroll
    for (int j = 0; j < 2; j++) { cpa16(adst[j], asrc[j]); cpa16(bdst[j], bsrc[j]); }
    cp_commit();

    #pragma unroll 1
    for (int kt = 0; kt < KIT; kt++) {
        const int s = kt & 1;
        cp_wait0();
        __syncthreads();
        if (kt + 1 < KIT) {
            const uint32_t so = (uint32_t)(s ^ 1) * STAGE;
            #pragma unroll
            for (int j = 0; j < 2; j++) {
                cpa16(adst[j] + so, asrc[j] + (size_t)(kt + 1) * 32);
                cpa16(bdst[j] + so, bsrc[j] + (size_t)(kt + 1) * 32);
            }
            cp_commit();
        }
        const uint32_t sb = (uint32_t)s * STAGE;
        #pragma unroll
        for (int kk = 0; kk < 2; kk++) {       // two k16 steps (byte offset 0 / 32)
            const uint32_t ko = sb + kk * 32u;
            uint32_t a[2][4];
            ldsm4(a[0], aoff[0] + ko);
            ldsm4(a[1], aoff[1] + ko);
            #pragma unroll
            for (int np = 0; np < 4; np++) {   // B LDSM interleaved with its 4 MMAs
                uint32_t b[4];
                ldsm4(b, boff[np] + ko);
                mma_f16(acc[0][2*np    ], a[0], b[0], b[1]);
                mma_f16(acc[1][2*np    ], a[1], b[0], b[1]);
                mma_f16(acc[0][2*np + 1], a[0], b[2], b[3]);
                mma_f16(acc[1][2*np + 1], a[1], b[2], b[3]);
            }
        }
    }

    // epilogue: bias (+gelu), write C
    const float* bp = bias + (size_t)e * NTOT + nt * 128 + wn * 64;
    const size_t cbase = ((size_t)e * CAPACITY + mt * 128 + wm * 32) * (size_t)NTOT
                       + (size_t)nt * 128 + wn * 64;
    #pragma unroll
    for (int mf = 0; mf < 2; mf++) {
        #pragma unroll
        for (int nf = 0; nf < 8; nf++) {
            int r  = mf * 16 + (lane >> 2);
            int cn = nf * 8 + 2 * (lane & 3);
            float bb0 = bp[cn], bb1 = bp[cn + 1];
            float v0 = acc[mf][nf][0] + bb0, v1 = acc[mf][nf][1] + bb1;
            float v2 = acc[mf][nf][2] + bb0, v3 = acc[mf][nf][3] + bb1;
            if (FIRST) {
                __half2 h01 = __floats2half2_rn(gelu_exact(v0), gelu_exact(v1));
                __half2 h23 = __floats2half2_rn(gelu_exact(v2), gelu_exact(v3));
                *(__half2*)(g_h + cbase + (size_t)r * NTOT + cn)       = h01;
                *(__half2*)(g_h + cbase + (size_t)(r + 8) * NTOT + cn) = h23;
            } else {
                *(float2*)(g_y + cbase + (size_t)r * NTOT + cn)       = make_float2(v0, v1);
                *(float2*)(g_y + cbase + (size_t)(r + 8) * NTOT + cn) = make_float2(v2, v3);
            }
        }
    }
}

// ---------------- 4) combine ----------------
__global__ void combine_kernel(float* __restrict__ out) {
    const int idx = blockIdx.x * blockDim.x + threadIdx.x;
    const int tok = idx >> 10;
    const int col = idx & (D_MODEL - 1);
    float acc = 0.f;
    #pragma unroll
    for (int kk = 0; kk < 2; kk++) {
        int a = 2 * tok + kk;
        int p = g_pos[a];
        if (p < CAPACITY) {
            int ee = g_expert[a];
            acc += g_gate[a] * g_y[((size_t)ee * CAPACITY + p) * D_MODEL + col];
        }
    }
    out[idx] = acc;
}

// ---------------- launch ----------------
extern "C" void kernel_launch(void* const* d_in, const int* in_sizes, int n_in,
                              void* d_out, int out_size) {
    (void)in_sizes; (void)n_in; (void)out_size;
    const float* x  = (const float*)d_in[0];
    const float* Wr = (const float*)d_in[1];
    const float* br = (const float*)d_in[2];
    const float* W1 = (const float*)d_in[3];
    const float* b1 = (const float*)d_in[4];
    const float* W2 = (const float*)d_in[5];
    const float* b2 = (const float*)d_in[6];
    float* out = (float*)d_out;

    __half *xh_p, *w1h_p, *w2h_p;
    cudaGetSymbolAddress((void**)&xh_p,  g_xh);
    cudaGetSymbolAddress((void**)&w1h_p, g_w1h);
    cudaGetSymbolAddress((void**)&w2h_p, g_w2h);

    // x: fp16 convert; W1/W2: fp16 convert + transpose to [N][K]
    {
        const int nx8 = T_TOK * D_MODEL / 8;
        f2h_kernel<<<(nx8 + 255) / 256, 256>>>((const float4*)x, (uint4*)xh_p, nx8);
        dim3 blk(32, 8);
        conv_transpose_kernel<<<dim3(F_FF / 32,    D_MODEL / 32, N_EXP), blk>>>(W1, w1h_p, D_MODEL, F_FF);
        conv_transpose_kernel<<<dim3(D_MODEL / 32, F_FF / 32,    N_EXP), blk>>>(W2, w2h_p, F_FF, D_MODEL);
    }

    router_kernel<<<T_TOK / 8, 256>>>(x, Wr, br);
    assign_kernel<<<1, 1024>>>();
    moe_gemm<true ><<<dim3(F_FF / 128,    CAPACITY / 128, N_EXP), 256>>>(xh_p,    w1h_p, b1);
    moe_gemm<false><<<dim3(D_MODEL / 128, CAPACITY / 128, N_EXP), 256>>>(nullptr, w2h_p, b2);
    combine_kernel<<<(T_TOK * D_MODEL) / 256, 256>>>(out);
}

// round 17
// speedup vs baseline: 2.3851x; 1.0305x over previous
#include <cuda_runtime.h>
#include <cuda_fp16.h>
#include <cstdint>
#include <cmath>
#include <math.h>

// Problem constants (fixed by setup_inputs)
#define T_TOK    8192
#define D_MODEL  1024
#define F_FF     4096
#define N_EXP    8
#define CAPACITY 2560          // ceil(1.25 * 8192*2 / 8)
#define NASSIGN  (T_TOK * 2)

// ---------------- scratch (device globals: no allocation allowed) ----------------
__device__ int    g_expert[NASSIGN];
__device__ float  g_gate[NASSIGN];
__device__ int    g_pos[NASSIGN];
__device__ int    g_count[N_EXP];
__device__ int    g_rowtok[N_EXP * CAPACITY];
__device__ __half g_h[(size_t)N_EXP * CAPACITY * F_FF];     // 168 MB (fp16, K-major)
__device__ float  g_y[(size_t)N_EXP * CAPACITY * D_MODEL];  //  84 MB
// pre-converted fp16 operands
__device__ __half g_xh [(size_t)T_TOK * D_MODEL];             // x, row-major [T][d]
__device__ __half g_w1h[(size_t)N_EXP * F_FF * D_MODEL];      // W1^T: [e][f][d] (K-major, K=d)
__device__ __half g_w2h[(size_t)N_EXP * D_MODEL * F_FF];      // W2^T: [e][d][f] (K-major, K=f)

// ---------------- helpers ----------------
__device__ __forceinline__ uint32_t su32(const void* p) {
    return (uint32_t)__cvta_generic_to_shared(p);
}
__device__ __forceinline__ void cpa16(uint32_t d, const void* s) {
    asm volatile("cp.async.cg.shared.global [%0], [%1], 16;" :: "r"(d), "l"(s));
}
__device__ __forceinline__ void cp_commit() { asm volatile("cp.async.commit_group;"); }
template <int N>
__device__ __forceinline__ void cp_wait() {
    asm volatile("cp.async.wait_group %0;" :: "n"(N) : "memory");
}

// m16n8k16 fp16 MMA, fp32 accumulate
__device__ __forceinline__ void mma_f16(float* c, const uint32_t* a, uint32_t b0, uint32_t b1) {
    asm volatile(
        "mma.sync.aligned.m16n8k16.row.col.f32.f16.f16.f32 "
        "{%0,%1,%2,%3}, {%4,%5,%6,%7}, {%8,%9}, {%0,%1,%2,%3};"
        : "+f"(c[0]), "+f"(c[1]), "+f"(c[2]), "+f"(c[3])
        : "r"(a[0]), "r"(a[1]), "r"(a[2]), "r"(a[3]), "r"(b0), "r"(b1));
}
__device__ __forceinline__ void ldsm4(uint32_t* r, uint32_t a) {
    asm volatile("ldmatrix.sync.aligned.m8n8.x4.shared.b16 {%0,%1,%2,%3}, [%4];"
        : "=r"(r[0]), "=r"(r[1]), "=r"(r[2]), "=r"(r[3]) : "r"(a));
}
__device__ __forceinline__ float gelu_exact(float v) {
    return 0.5f * v * (1.0f + erff(v * 0.70710678118654752440f));
}

// ---------------- 0a) fp16 convert (x: no transpose), 8 elems/thread ----------------
__global__ void f2h_kernel(const float4* __restrict__ src, uint4* __restrict__ dst, int n8) {
    int i = blockIdx.x * blockDim.x + threadIdx.x;
    if (i < n8) {
        float4 v0 = src[2 * i], v1 = src[2 * i + 1];
        __half2 h0 = __floats2half2_rn(v0.x, v0.y);
        __half2 h1 = __floats2half2_rn(v0.z, v0.w);
        __half2 h2 = __floats2half2_rn(v1.x, v1.y);
        __half2 h3 = __floats2half2_rn(v1.z, v1.w);
        uint4 o;
        o.x = *(uint32_t*)&h0; o.y = *(uint32_t*)&h1;
        o.z = *(uint32_t*)&h2; o.w = *(uint32_t*)&h3;
        dst[i] = o;
    }
}

// ---------------- 0b) fp16 convert + transpose: dst[e][c][r] = h(src[e][r][c]) -------
__global__ void conv_transpose_kernel(const float* __restrict__ src, __half* __restrict__ dst,
                                      int R, int C) {
    __shared__ unsigned short tile[32][33];
    const int e  = blockIdx.z;
    const float* s = src + (size_t)e * R * C;
    __half*      d = dst + (size_t)e * R * C;
    const int c0 = blockIdx.x * 32, r0 = blockIdx.y * 32;
    #pragma unroll
    for (int i = 0; i < 4; i++) {
        int r = r0 + threadIdx.y + i * 8;
        __half h = __float2half_rn(s[(size_t)r * C + c0 + threadIdx.x]);
        tile[threadIdx.y + i * 8][threadIdx.x] = *(unsigned short*)&h;
    }
    __syncthreads();
    #pragma unroll
    for (int i = 0; i < 4; i++) {
        int rr = threadIdx.y + i * 8;
        unsigned short u = tile[threadIdx.x][rr];
        d[(size_t)(c0 + rr) * R + r0 + threadIdx.x] = *(__half*)&u;
    }
}

// ---------------- 1) router ----------------
__global__ void router_kernel(const float* __restrict__ x,
                              const float* __restrict__ Wr,
                              const float* __restrict__ br) {
    __shared__ float sW[D_MODEL * N_EXP];
    const int tid = threadIdx.x;
    for (int i = tid; i < D_MODEL * N_EXP / 4; i += blockDim.x)
        ((float4*)sW)[i] = ((const float4*)Wr)[i];
    __syncthreads();

    const int warp = tid >> 5, lane = tid & 31;
    const int tok = blockIdx.x * 8 + warp;
    const float* xr = x + (size_t)tok * D_MODEL;

    float a[8] = {0.f,0.f,0.f,0.f,0.f,0.f,0.f,0.f};
    for (int i = lane; i < D_MODEL; i += 32) {
        float xv = xr[i];
        const float* w = sW + i * N_EXP;
        #pragma unroll
        for (int e = 0; e < 8; e++) a[e] += xv * w[e];
    }
    #pragma unroll
    for (int e = 0; e < 8; e++) {
        #pragma unroll
        for (int off = 16; off; off >>= 1)
            a[e] += __shfl_xor_sync(0xffffffffu, a[e], off);
    }
    if (lane == 0) {
        #pragma unroll
        for (int e = 0; e < 8; e++) a[e] += br[e];
        int e0 = 0; float l0 = a[0];
        #pragma unroll
        for (int e = 1; e < 8; e++) if (a[e] > l0) { l0 = a[e]; e0 = e; }
        int e1 = -1; float l1 = -1e30f;
        #pragma unroll
        for (int e = 0; e < 8; e++) if (e != e0 && a[e] > l1) { l1 = a[e]; e1 = e; }
        float w0 = 1.f / (1.f + expf(l1 - l0));
        float w1 = 1.f / (1.f + expf(l0 - l1));
        g_expert[2*tok]   = e0;  g_expert[2*tok+1] = e1;
        g_gate[2*tok]     = w0;  g_gate[2*tok+1]   = w1;
    }
}

// ---------------- 2) FCFS positions + per-expert gather lists ----------------
__global__ void assign_kernel() {
    __shared__ int sc[1024][9];
    const int t = threadIdx.x;
    const int base = t * 16;

    #pragma unroll
    for (int e = 0; e < 8; e++) sc[t][e] = 0;
    for (int i = 0; i < 16; i++) sc[t][g_expert[base + i]]++;

    int loc[8], run[8];
    #pragma unroll
    for (int e = 0; e < 8; e++) { loc[e] = sc[t][e]; run[e] = loc[e]; }
    __syncthreads();

    for (int off = 1; off < 1024; off <<= 1) {
        int add[8];
        #pragma unroll
        for (int e = 0; e < 8; e++) add[e] = (t >= off) ? sc[t - off][e] : 0;
        __syncthreads();
        #pragma unroll
        for (int e = 0; e < 8; e++) { run[e] += add[e]; sc[t][e] = run[e]; }
        __syncthreads();
    }
    if (t == 1023) {
        #pragma unroll
        for (int e = 0; e < 8; e++)
            g_count[e] = run[e] < CAPACITY ? run[e] : CAPACITY;
    }
    #pragma unroll
    for (int e = 0; e < 8; e++) sc[t][e] = run[e] - loc[e];
    for (int i = 0; i < 16; i++) {
        int a = base + i;
        int e = g_expert[a];
        int p = sc[t][e]++;
        g_pos[a] = p;
        if (p < CAPACITY) g_rowtok[e * CAPACITY + p] = a >> 1;
    }
}

// ---------------- 3) grouped fp16 GEMM, 128x128 CTA tile, 32x64 warp tiles ----------
// 8 warps / 256 threads. 3-stage cp.async ring (k32 fp16 stages, 80B row stride,
// conflict-free ldmatrix), single __syncthreads per stage, wait_group 1
// (wait_group 0 on the FINAL stage — the R16 bug was reading the last stage
// while its cp.async group could still be in flight).
template <bool FIRST>
__global__ __launch_bounds__(256, 2)
void moe_gemm(const __half* __restrict__ X,
              const __half* __restrict__ W,
              const float* __restrict__ bias) {
    constexpr int KTOT = FIRST ? D_MODEL : F_FF;
    constexpr int NTOT = FIRST ? F_FF : D_MODEL;
    constexpr int KIT  = KTOT / 32;
    constexpr uint32_t OSTAGE = 128 * 40 * 2;     // bytes per operand stage (10 KB)
    constexpr uint32_t BOFF   = 3 * OSTAGE;       // B region starts after 3 A stages

    extern __shared__ __align__(16) __half sm[];
    const uint32_t abase = su32(sm);

    const int e = blockIdx.z, mt = blockIdx.y, nt = blockIdx.x;
    const int cnt = g_count[e];
    if (mt * 128 >= cnt) return;

    const int tid = threadIdx.x, lane = tid & 31, warp = tid >> 5;
    const int wm = warp & 3, wn = warp >> 2;   // 4 (M) x 2 (N) warps -> 32x64 warp tiles

    const __half* Ain = FIRST ? X : (const __half*)g_h;

    // per-thread cp.async assignments: 2 A chunks + 2 B chunks of 16B per k32 stage
    const __half* asrc[2]; uint32_t adst[2];
    const __half* bsrc[2]; uint32_t bdst[2];
    #pragma unroll
    for (int j = 0; j < 2; j++) {
        int c = tid + j * 256;                // 0..511
        int row = c >> 2, seg = (c & 3) * 8;  // 4 x 16B (8 halves) per 32-half row
        if (FIRST) {
            int gr = mt * 128 + row;
            int tk = (gr < cnt) ? g_rowtok[e * CAPACITY + gr] : 0;  // safe garbage row
            asrc[j] = Ain + (size_t)tk * KTOT + seg;
        } else {
            asrc[j] = Ain + ((size_t)e * CAPACITY + mt * 128 + row) * (size_t)KTOT + seg;
        }
        adst[j] = abase + (uint32_t)(row * 80 + seg * 2);
        bsrc[j] = W + ((size_t)e * NTOT + nt * 128 + row) * (size_t)KTOT + seg;
        bdst[j] = abase + BOFF + (uint32_t)(row * 80 + seg * 2);
    }

    auto load_stage = [&](int kt) {
        const uint32_t so = (uint32_t)(kt % 3) * OSTAGE;
        const size_t   ke = (size_t)kt * 32;
        #pragma unroll
        for (int j = 0; j < 2; j++) {
            cpa16(adst[j] + so, asrc[j] + ke);
            cpa16(bdst[j] + so, bsrc[j] + ke);
        }
        cp_commit();
    };

    // ldmatrix lane addresses (canonical fp16 m16n8k16 fragment mapping)
    uint32_t aoff[2], boff[4];
    #pragma unroll
    for (int mf = 0; mf < 2; mf++) {
        int row = wm * 32 + mf * 16 + ((lane >> 3) & 1) * 8 + (lane & 7);
        aoff[mf] = abase + (uint32_t)row * 80u + ((lane >> 4) & 1) * 16u;
    }
    #pragma unroll
    for (int np = 0; np < 4; np++) {
        int row = wn * 64 + np * 16 + ((lane >> 4) & 1) * 8 + (lane & 7);
        boff[np] = abase + BOFF + (uint32_t)row * 80u + ((lane >> 3) & 1) * 16u;
    }

    float acc[2][8][4];
    #pragma unroll
    for (int mf = 0; mf < 2; mf++)
        #pragma unroll
        for (int nf = 0; nf < 8; nf++)
            #pragma unroll
            for (int q = 0; q < 4; q++) acc[mf][nf][q] = 0.f;

    // prologue: stages 0 and 1 in flight
    load_stage(0);
    load_stage(1);

    #pragma unroll 1
    for (int kt = 0; kt < KIT; kt++) {
        if (kt + 1 < KIT) cp_wait<1>();  // stage kt landed; kt+1 may be in flight
        else              cp_wait<0>();  // FINAL stage: full drain (R16 bugfix)
        __syncthreads();       // data visible; all warps done reading buf (kt-1)%3
        if (kt + 2 < KIT) load_stage(kt + 2);   // fills buf (kt-1)%3 — safe post-barrier
        const uint32_t so = (uint32_t)(kt % 3) * OSTAGE;
        #pragma unroll
        for (int kk = 0; kk < 2; kk++) {       // two k16 steps (byte offset 0 / 32)
            const uint32_t ko = so + kk * 32u;
            uint32_t a[2][4];
            ldsm4(a[0], aoff[0] + ko);
            ldsm4(a[1], aoff[1] + ko);
            #pragma unroll
            for (int np = 0; np < 4; np++) {   // B LDSM interleaved with its 4 MMAs
                uint32_t b[4];
                ldsm4(b, boff[np] + ko);
                mma_f16(acc[0][2*np    ], a[0], b[0], b[1]);
                mma_f16(acc[1][2*np    ], a[1], b[0], b[1]);
                mma_f16(acc[0][2*np + 1], a[0], b[2], b[3]);
                mma_f16(acc[1][2*np + 1], a[1], b[2], b[3]);
            }
        }
    }

    // epilogue: bias (+gelu), write C
    const float* bp = bias + (size_t)e * NTOT + nt * 128 + wn * 64;
    const size_t cbase = ((size_t)e * CAPACITY + mt * 128 + wm * 32) * (size_t)NTOT
                       + (size_t)nt * 128 + wn * 64;
    #pragma unroll
    for (int mf = 0; mf < 2; mf++) {
        #pragma unroll
        for (int nf = 0; nf < 8; nf++) {
            int r  = mf * 16 + (lane >> 2);
            int cn = nf * 8 + 2 * (lane & 3);
            float bb0 = bp[cn], bb1 = bp[cn + 1];
            float v0 = acc[mf][nf][0] + bb0, v1 = acc[mf][nf][1] + bb1;
            float v2 = acc[mf][nf][2] + bb0, v3 = acc[mf][nf][3] + bb1;
            if (FIRST) {
                __half2 h01 = __floats2half2_rn(gelu_exact(v0), gelu_exact(v1));
                __half2 h23 = __floats2half2_rn(gelu_exact(v2), gelu_exact(v3));
                *(__half2*)(g_h + cbase + (size_t)r * NTOT + cn)       = h01;
                *(__half2*)(g_h + cbase + (size_t)(r + 8) * NTOT + cn) = h23;
            } else {
                *(float2*)(g_y + cbase + (size_t)r * NTOT + cn)       = make_float2(v0, v1);
                *(float2*)(g_y + cbase + (size_t)(r + 8) * NTOT + cn) = make_float2(v2, v3);
            }
        }
    }
}

// ---------------- 4) combine ----------------
__global__ void combine_kernel(float* __restrict__ out) {
    const int idx = blockIdx.x * blockDim.x + threadIdx.x;
    const int tok = idx >> 10;
    const int col = idx & (D_MODEL - 1);
    float acc = 0.f;
    #pragma unroll
    for (int kk = 0; kk < 2; kk++) {
        int a = 2 * tok + kk;
        int p = g_pos[a];
        if (p < CAPACITY) {
            int ee = g_expert[a];
            acc += g_gate[a] * g_y[((size_t)ee * CAPACITY + p) * D_MODEL + col];
        }
    }
    out[idx] = acc;
}

// ---------------- launch ----------------
extern "C" void kernel_launch(void* const* d_in, const int* in_sizes, int n_in,
                              void* d_out, int out_size) {
    (void)in_sizes; (void)n_in; (void)out_size;
    const float* x  = (const float*)d_in[0];
    const float* Wr = (const float*)d_in[1];
    const float* br = (const float*)d_in[2];
    const float* W1 = (const float*)d_in[3];
    const float* b1 = (const float*)d_in[4];
    const float* W2 = (const float*)d_in[5];
    const float* b2 = (const float*)d_in[6];
    float* out = (float*)d_out;

    __half *xh_p, *w1h_p, *w2h_p;
    cudaGetSymbolAddress((void**)&xh_p,  g_xh);
    cudaGetSymbolAddress((void**)&w1h_p, g_w1h);
    cudaGetSymbolAddress((void**)&w2h_p, g_w2h);

    // 3-stage ring: 6 operand stages x 10KB = 60KB dynamic smem
    const int SMEM_DYN = 6 * 128 * 40 * 2;
    cudaFuncSetAttribute(moe_gemm<true >, cudaFuncAttributeMaxDynamicSharedMemorySize, SMEM_DYN);
    cudaFuncSetAttribute(moe_gemm<false>, cudaFuncAttributeMaxDynamicSharedMemorySize, SMEM_DYN);

    // x: fp16 convert; W1/W2: fp16 convert + transpose to [N][K]
    {
        const int nx8 = T_TOK * D_MODEL / 8;
        f2h_kernel<<<(nx8 + 255) / 256, 256>>>((const float4*)x, (uint4*)xh_p, nx8);
        dim3 blk(32, 8);
        conv_transpose_kernel<<<dim3(F_FF / 32,    D_MODEL / 32, N_EXP), blk>>>(W1, w1h_p, D_MODEL, F_FF);
        conv_transpose_kernel<<<dim3(D_MODEL / 32, F_FF / 32,    N_EXP), blk>>>(W2, w2h_p, F_FF, D_MODEL);
    }

    router_kernel<<<T_TOK / 8, 256>>>(x, Wr, br);
    assign_kernel<<<1, 1024>>>();
    moe_gemm<true ><<<dim3(F_FF / 128,    CAPACITY / 128, N_EXP), 256, SMEM_DYN>>>(xh_p,    w1h_p, b1);
    moe_gemm<false><<<dim3(D_MODEL / 128, CAPACITY / 128, N_EXP), 256, SMEM_DYN>>>(nullptr, w2h_p, b2);
    combine_kernel<<<(T_TOK * D_MODEL) / 256, 256>>>(out);
}